// round 1
// baseline (speedup 1.0000x reference)
#include <cuda_runtime.h>
#include <math.h>

#define NPTS 400000
#define KOFF 27
#define CO 38
#define CO_PAD 40
#define BM 256
#define NTHREADS 256

// Intermediate activations (layer1 output, post-GELU). Zero row for padding
// handled via g_zero pointer substitution instead, so no init pass needed.
__device__ float g_h[(size_t)NPTS * CO];
__device__ float g_zero[64];  // static zero-init; never written

__device__ __forceinline__ unsigned long long pack2(float lo, float hi) {
    unsigned long long r;
    asm("mov.b64 %0, {%1, %2};" : "=l"(r) : "f"(lo), "f"(hi));
    return r;
}
__device__ __forceinline__ void unpack2(float& lo, float& hi, unsigned long long v) {
    asm("mov.b64 {%0, %1}, %2;" : "=f"(lo), "=f"(hi) : "l"(v));
}
// Packed dual-FMA: d = a*b + c per 32-bit lane. ptxas emits FFMA2 (2x scalar FFMA tput).
__device__ __forceinline__ unsigned long long fma2(unsigned long long a,
                                                   unsigned long long b,
                                                   unsigned long long c) {
    unsigned long long d;
    asm("fma.rn.f32x2 %0, %1, %2, %3;" : "=l"(d) : "l"(a), "l"(b), "l"(c));
    return d;
}

// One sparse-conv layer: out[i,:] = sum_k W[k]^T feat[nbr[k,i],:]  (+ optional exact GELU)
// Thread tile: 4 points x 10 output channels (CO padded to 40).
// f32x2 packing over channel pairs: weight pairs load directly as LDS.64.
template <int CI, bool DO_GELU, bool IN_IS_H, bool OUT_IS_H>
__global__ __launch_bounds__(NTHREADS) void conv_kernel(
    const float* __restrict__ feat_in,
    const int* __restrict__ nbr,
    const float* __restrict__ W,
    float* __restrict__ out_p)
{
    __shared__ __align__(16) float Ws[CI * CO_PAD];
    __shared__ int nbr_s[BM];

    const float* feat = IN_IS_H ? g_h : feat_in;
    float* out = OUT_IS_H ? g_h : out_p;

    const int t = threadIdx.x;
    const int cg = t & 3;        // channel group: cols [cg*10, cg*10+10)
    const int rg = t >> 2;       // row group: 4 points
    const int i0 = blockIdx.x * BM;
    const int mbase = i0 + rg * 4;

    unsigned long long acc[4][5];
#pragma unroll
    for (int p = 0; p < 4; ++p)
#pragma unroll
        for (int q = 0; q < 5; ++q) acc[p][q] = 0ull;  // two packed 0.0f

    for (int k = 0; k < KOFF; ++k) {
        __syncthreads();  // protect smem reuse from previous iteration
        // Stage W[k] into smem, zero-padding cols [CO, CO_PAD)
        for (int idx = t; idx < CI * CO_PAD; idx += NTHREADS) {
            int j = idx / CO_PAD;
            int c = idx - j * CO_PAD;
            Ws[idx] = (c < CO) ? W[(k * CI + j) * CO + c] : 0.0f;
        }
        // Stage neighbor indices for this tile
        {
            int gi = i0 + t;
            nbr_s[t] = (gi < NPTS) ? nbr[k * NPTS + gi] : NPTS;
        }
        __syncthreads();

        const float* rowp[4];
#pragma unroll
        for (int p = 0; p < 4; ++p) {
            int idx = nbr_s[rg * 4 + p];
            rowp[p] = (idx < NPTS) ? (feat + (size_t)idx * CI) : g_zero;
        }

#pragma unroll 8
        for (int j = 0; j < CI; ++j) {
            unsigned long long f2[4];
#pragma unroll
            for (int p = 0; p < 4; ++p) {
                float fv = rowp[p][j];
                f2[p] = pack2(fv, fv);
            }
            const unsigned long long* wrow =
                reinterpret_cast<const unsigned long long*>(Ws + j * CO_PAD + cg * 10);
#pragma unroll
            for (int q = 0; q < 5; ++q) {
                unsigned long long w2 = wrow[q];
#pragma unroll
                for (int p = 0; p < 4; ++p) acc[p][q] = fma2(f2[p], w2, acc[p][q]);
            }
        }
    }

    // Epilogue: unpack, optional exact GELU, store valid cols/rows
#pragma unroll
    for (int p = 0; p < 4; ++p) {
        int row = mbase + p;
        if (row >= NPTS) continue;
#pragma unroll
        for (int q = 0; q < 5; ++q) {
            float lo, hi;
            unpack2(lo, hi, acc[p][q]);
            int c = cg * 10 + 2 * q;
            if (DO_GELU) {
                lo = 0.5f * lo * (1.0f + erff(lo * 0.70710678118654752f));
                hi = 0.5f * hi * (1.0f + erff(hi * 0.70710678118654752f));
            }
            if (c < CO)     out[(size_t)row * CO + c]     = lo;
            if (c + 1 < CO) out[(size_t)row * CO + c + 1] = hi;
        }
    }
}

extern "C" void kernel_launch(void* const* d_in, const int* in_sizes, int n_in,
                              void* d_out, int out_size) {
    const float* feat = (const float*)d_in[0];   // [N, 64] f32
    const int* nbr    = (const int*)d_in[1];     // [27, N] i32
    const float* W1   = (const float*)d_in[2];   // [27, 64, 38] f32
    const float* W2   = (const float*)d_in[3];   // [27, 38, 38] f32
    float* out        = (float*)d_out;           // [N, 38] f32

    const int grid = (NPTS + BM - 1) / BM;
    conv_kernel<64, true,  false, true ><<<grid, NTHREADS>>>(feat, nbr, W1, nullptr);
    conv_kernel<38, false, true,  false><<<grid, NTHREADS>>>(nullptr, nbr, W2, out);
}

// round 7
// speedup vs baseline: 1.2620x; 1.2620x over previous
#include <cuda_runtime.h>
#include <cuda_bf16.h>
#include <cstdint>
#include <math.h>

#define NPTS   400000
#define KOFF   27
#define TILE_M 128
#define NTILES (NPTS / TILE_M)    // 3125 exact
#define CPAD   64                 // padded channel dim -> 128B bf16 rows
#define NOUT   38
#define NPADB  40                 // MMA N (5 x n8 tiles)

// ---------------- global scratch (static zero-init; no allocation) ----------------
__device__ __nv_bfloat16 g_fhi[(size_t)(NPTS + 1) * CPAD];
__device__ __nv_bfloat16 g_flo[(size_t)(NPTS + 1) * CPAD];
__device__ __nv_bfloat16 g_hhi[(size_t)(NPTS + 1) * CPAD];
__device__ __nv_bfloat16 g_hlo[(size_t)(NPTS + 1) * CPAD];
__device__ __nv_bfloat16 g_w1hi[KOFF * NPADB * CPAD];
__device__ __nv_bfloat16 g_w1lo[KOFF * NPADB * CPAD];
__device__ __nv_bfloat16 g_w2hi[KOFF * NPADB * CPAD];
__device__ __nv_bfloat16 g_w2lo[KOFF * NPADB * CPAD];

// ---------------- helpers ----------------
__device__ __forceinline__ uint32_t smem_u32(const void* p) {
    uint32_t a;
    asm("{ .reg .u64 t; cvta.to.shared.u64 t, %1; cvt.u32.u64 %0, t; }" : "=r"(a) : "l"(p));
    return a;
}
#define SWZ(o) (((uint32_t)(o)) ^ ((((uint32_t)(o)) >> 3) & 0x70))

__device__ __forceinline__ void ldsm_x4(uint32_t* r, uint32_t addr) {
    asm volatile("ldmatrix.sync.aligned.m8n8.x4.shared.b16 {%0,%1,%2,%3}, [%4];"
                 : "=r"(r[0]), "=r"(r[1]), "=r"(r[2]), "=r"(r[3]) : "r"(addr));
}
__device__ __forceinline__ void ldsm_x2(uint32_t* r, uint32_t addr) {
    asm volatile("ldmatrix.sync.aligned.m8n8.x2.shared.b16 {%0,%1}, [%2];"
                 : "=r"(r[0]), "=r"(r[1]) : "r"(addr));
}
__device__ __forceinline__ void mma_bf16(float* d, const uint32_t* a, uint32_t b0, uint32_t b1) {
    asm volatile("mma.sync.aligned.m16n8k16.row.col.f32.bf16.bf16.f32 "
                 "{%0,%1,%2,%3}, {%4,%5,%6,%7}, {%8,%9}, {%0,%1,%2,%3};"
                 : "+f"(d[0]), "+f"(d[1]), "+f"(d[2]), "+f"(d[3])
                 : "r"(a[0]), "r"(a[1]), "r"(a[2]), "r"(a[3]), "r"(b0), "r"(b1));
}

// ---------------- smem layout ----------------
#define AHI_OFF 0u       // 128 x 128B
#define ALO_OFF 16384u   // 128 x 128B
#define BHI_OFF 32768u   // 40 x 128B
#define BLO_OFF 37888u   // 40 x 128B
#define SMEM_BYTES 43008u

// ---------------- prep kernels ----------------
__global__ void prep_w(const float* __restrict__ W1, const float* __restrict__ W2) {
    int idx = blockIdx.x * 256 + threadIdx.x;
    if (idx >= KOFF * NPADB * CPAD) return;
    int j = idx & (CPAD - 1);
    int n = (idx / CPAD) % NPADB;
    int k = idx / (CPAD * NPADB);
    float w1 = (n < NOUT) ? W1[(k * 64 + j) * NOUT + n] : 0.0f;
    float w2 = (n < NOUT && j < NOUT) ? W2[(k * NOUT + j) * NOUT + n] : 0.0f;
    __nv_bfloat16 h1 = __float2bfloat16(w1);
    g_w1hi[idx] = h1;
    g_w1lo[idx] = __float2bfloat16(w1 - __bfloat162float(h1));
    __nv_bfloat16 h2 = __float2bfloat16(w2);
    g_w2hi[idx] = h2;
    g_w2lo[idx] = __float2bfloat16(w2 - __bfloat162float(h2));
}

__global__ void prep_f(const float* __restrict__ feat) {
    size_t idx = (size_t)blockIdx.x * 256 + threadIdx.x;
    if (idx >= (size_t)(NPTS + 1) * CPAD) return;
    size_t i = idx >> 6;
    float x = (i < NPTS) ? feat[idx] : 0.0f;
    __nv_bfloat16 h = __float2bfloat16(x);
    g_fhi[idx] = h;
    g_flo[idx] = __float2bfloat16(x - __bfloat162float(h));
    if (i == NPTS) {  // zero padding row of h
        g_hhi[idx] = __float2bfloat16(0.0f);
        g_hlo[idx] = __float2bfloat16(0.0f);
    }
}

// ---------------- main conv kernel (warp-level HMMA) ----------------
template <int NKS, bool LAYER2>
__global__ void __launch_bounds__(256, 4) conv_mma(const int* __restrict__ nbr,
                                                   float* __restrict__ out) {
    __shared__ __align__(1024) char smb[SMEM_BYTES];
    const uint32_t smu = smem_u32(smb);
    const int t = threadIdx.x;
    const int lane = t & 31;
    const int wid = t >> 5;
    const int m0 = wid * 16;              // 16 rows per warp
    const int i0 = blockIdx.x * TILE_M;

    const __nv_bfloat16* __restrict__ shi = LAYER2 ? g_hhi : g_fhi;
    const __nv_bfloat16* __restrict__ slo = LAYER2 ? g_hlo : g_flo;
    const __nv_bfloat16* __restrict__ whi = LAYER2 ? g_w2hi : g_w1hi;
    const __nv_bfloat16* __restrict__ wlo = LAYER2 ? g_w2lo : g_w1lo;

    float acc[5][4];
#pragma unroll
    for (int nt = 0; nt < 5; ++nt)
#pragma unroll
        for (int q = 0; q < 4; ++q) acc[nt][q] = 0.0f;

    // per-thread ldmatrix address components (constant across k)
    const int a_row = m0 + (lane & 7) + ((lane >> 3) & 1) * 8;  // A matrix row
    const int a_half = (lane >> 4) << 4;                         // 0 or 16 bytes
    const int b_r = lane & 7;                                    // B row within n8 group
    const int b_sub = (lane >> 3) & 3;                           // matrix idx 0..3

    for (int k = 0; k < KOFF; ++k) {
        __syncthreads();  // protect smem from previous iteration's readers
        // ---- gather A (hi+lo): 128 rows x 8 chunks of 16B, swizzled ----
#pragma unroll
        for (int i = 0; i < 4; ++i) {
            int q = t + 256 * i;       // 0..1023
            int row = q >> 3, c = q & 7;
            int nb = __ldg(nbr + (size_t)k * NPTS + i0 + row);
            size_t src = (size_t)nb * CPAD + c * 8;
            uint32_t off = SWZ(row * 128 + c * 16);
            *(uint4*)(smb + AHI_OFF + off) = *(const uint4*)(shi + src);
            *(uint4*)(smb + ALO_OFF + off) = *(const uint4*)(slo + src);
        }
        // ---- B tile (hi+lo): 40 rows x 8 chunks ----
        {
            const __nv_bfloat16* wkh = whi + k * (NPADB * CPAD);
            const __nv_bfloat16* wkl = wlo + k * (NPADB * CPAD);
#pragma unroll
            for (int i = 0; i < 2; ++i) {
                int q = t + 256 * i;
                if (q < NPADB * 8) {
                    int row = q >> 3, c = q & 7;
                    uint32_t off = SWZ(row * 128 + c * 16);
                    *(uint4*)(smb + BHI_OFF + off) = *(const uint4*)(wkh + row * CPAD + c * 8);
                    *(uint4*)(smb + BLO_OFF + off) = *(const uint4*)(wkl + row * CPAD + c * 8);
                }
            }
        }
        __syncthreads();

        // ---- compute: 3-pass bf16-split, fp32 accumulate ----
        uint32_t a[NKS][4];
#pragma unroll
        for (int ks = 0; ks < NKS; ++ks)
            ldsm_x4(a[ks], smu + AHI_OFF + SWZ(a_row * 128 + ks * 32 + a_half));

#pragma unroll
        for (int pass = 0; pass < 2; ++pass) {  // (Ahi,Bhi), (Ahi,Blo)
            const uint32_t bbase = smu + (pass == 0 ? BHI_OFF : BLO_OFF);
#pragma unroll
            for (int nt = 0; nt < 5; ++nt) {
                const int brow = nt * 8 + b_r;
#pragma unroll
                for (int ks2 = 0; ks2 < NKS / 2; ++ks2) {
                    uint32_t b4[4];
                    ldsm_x4(b4, bbase + SWZ(brow * 128 + ks2 * 64 + b_sub * 16));
                    mma_bf16(acc[nt], a[2 * ks2], b4[0], b4[1]);
                    mma_bf16(acc[nt], a[2 * ks2 + 1], b4[2], b4[3]);
                }
                if (NKS & 1) {
                    uint32_t b2[2];
                    ldsm_x2(b2, bbase + SWZ(brow * 128 + (NKS - 1) * 32 + (b_sub & 1) * 16));
                    mma_bf16(acc[nt], a[NKS - 1], b2[0], b2[1]);
                }
            }
        }
        // pass 2: (Alo, Bhi)
#pragma unroll
        for (int ks = 0; ks < NKS; ++ks)
            ldsm_x4(a[ks], smu + ALO_OFF + SWZ(a_row * 128 + ks * 32 + a_half));
        {
            const uint32_t bbase = smu + BHI_OFF;
#pragma unroll
            for (int nt = 0; nt < 5; ++nt) {
                const int brow = nt * 8 + b_r;
#pragma unroll
                for (int ks2 = 0; ks2 < NKS / 2; ++ks2) {
                    uint32_t b4[4];
                    ldsm_x4(b4, bbase + SWZ(brow * 128 + ks2 * 64 + b_sub * 16));
                    mma_bf16(acc[nt], a[2 * ks2], b4[0], b4[1]);
                    mma_bf16(acc[nt], a[2 * ks2 + 1], b4[2], b4[3]);
                }
                if (NKS & 1) {
                    uint32_t b2[2];
                    ldsm_x2(b2, bbase + SWZ(brow * 128 + (NKS - 1) * 32 + (b_sub & 1) * 16));
                    mma_bf16(acc[nt], a[NKS - 1], b2[0], b2[1]);
                }
            }
        }
    }

    // ---- epilogue ----
    // C frag: thread holds rows (r1, r1+8), cols nt*8 + (lane%4)*2, +1
    const int r1 = i0 + m0 + (lane >> 2);
#pragma unroll
    for (int half = 0; half < 2; ++half) {
        const int row = r1 + half * 8;
#pragma unroll
        for (int nt = 0; nt < 5; ++nt) {
            const int c = nt * 8 + (lane & 3) * 2;
            float v0 = acc[nt][half * 2 + 0];
            float v1 = acc[nt][half * 2 + 1];
            if (LAYER2) {
                if (c < NOUT) {
                    float* o = out + (size_t)row * NOUT + c;
                    o[0] = v0;
                    if (c + 1 < NOUT) o[1] = v1;
                }
            } else {
                v0 = 0.5f * v0 * (1.0f + erff(v0 * 0.7071067811865475f));
                v1 = 0.5f * v1 * (1.0f + erff(v1 * 0.7071067811865475f));
                __nv_bfloat16 h0 = __float2bfloat16(v0), h1 = __float2bfloat16(v1);
                __nv_bfloat162 hp; hp.x = h0; hp.y = h1;
                *(__nv_bfloat162*)(g_hhi + (size_t)row * CPAD + c) = hp;
                __nv_bfloat162 lp;
                lp.x = __float2bfloat16(v0 - __bfloat162float(h0));
                lp.y = __float2bfloat16(v1 - __bfloat162float(h1));
                *(__nv_bfloat162*)(g_hlo + (size_t)row * CPAD + c) = lp;
            }
        }
    }
}

// ---------------- launch ----------------
extern "C" void kernel_launch(void* const* d_in, const int* in_sizes, int n_in,
                              void* d_out, int out_size) {
    const float* feat = (const float*)d_in[0];  // [N, 64] f32
    const int* nbr    = (const int*)d_in[1];    // [27, N] i32
    const float* W1   = (const float*)d_in[2];  // [27, 64, 38] f32
    const float* W2   = (const float*)d_in[3];  // [27, 38, 38] f32
    float* out        = (float*)d_out;          // [N, 38] f32

    prep_w<<<(KOFF * NPADB * CPAD + 255) / 256, 256>>>(W1, W2);
    {
        size_t tot = (size_t)(NPTS + 1) * CPAD;
        prep_f<<<(unsigned)((tot + 255) / 256), 256>>>(feat);
    }
    conv_mma<4, false><<<NTILES, 256>>>(nbr, nullptr);  // layer1: K=64, GELU -> g_h (hi/lo)
    conv_mma<3, true ><<<NTILES, 256>>>(nbr, out);      // layer2: K=48 (38 padded)
}

// round 8
// speedup vs baseline: 2.2450x; 1.7790x over previous
#include <cuda_runtime.h>
#include <cuda_bf16.h>
#include <cstdint>
#include <math.h>

#define NPTS   400000
#define KOFF   27
#define TILE_M 128
#define NTILES (NPTS / TILE_M)    // 3125 exact
#define CPAD   64                 // padded channel dim -> 128B bf16 rows
#define NOUT   38
#define NPADB  40                 // MMA N (5 x n8 tiles)

// ---------------- global scratch (static zero-init; no allocation) ----------------
__device__ __nv_bfloat16 g_fhi[(size_t)(NPTS + 1) * CPAD];
__device__ __nv_bfloat16 g_flo[(size_t)(NPTS + 1) * CPAD];
__device__ __nv_bfloat16 g_hhi[(size_t)(NPTS + 1) * CPAD];
__device__ __nv_bfloat16 g_hlo[(size_t)(NPTS + 1) * CPAD];
__device__ __nv_bfloat16 g_w1hi[KOFF * NPADB * CPAD];
__device__ __nv_bfloat16 g_w1lo[KOFF * NPADB * CPAD];
__device__ __nv_bfloat16 g_w2hi[KOFF * NPADB * CPAD];
__device__ __nv_bfloat16 g_w2lo[KOFF * NPADB * CPAD];

// ---------------- helpers ----------------
__device__ __forceinline__ uint32_t smem_u32(const void* p) {
    uint32_t a;
    asm("{ .reg .u64 t; cvta.to.shared.u64 t, %1; cvt.u32.u64 %0, t; }" : "=r"(a) : "l"(p));
    return a;
}
#define SWZ(o) (((uint32_t)(o)) ^ ((((uint32_t)(o)) >> 3) & 0x70))

__device__ __forceinline__ void ldsm_x4(uint32_t* r, uint32_t addr) {
    asm volatile("ldmatrix.sync.aligned.m8n8.x4.shared.b16 {%0,%1,%2,%3}, [%4];"
                 : "=r"(r[0]), "=r"(r[1]), "=r"(r[2]), "=r"(r[3]) : "r"(addr));
}
__device__ __forceinline__ void ldsm_x2(uint32_t* r, uint32_t addr) {
    asm volatile("ldmatrix.sync.aligned.m8n8.x2.shared.b16 {%0,%1}, [%2];"
                 : "=r"(r[0]), "=r"(r[1]) : "r"(addr));
}
__device__ __forceinline__ void mma_bf16(float* d, const uint32_t* a, uint32_t b0, uint32_t b1) {
    asm volatile("mma.sync.aligned.m16n8k16.row.col.f32.bf16.bf16.f32 "
                 "{%0,%1,%2,%3}, {%4,%5,%6,%7}, {%8,%9}, {%0,%1,%2,%3};"
                 : "+f"(d[0]), "+f"(d[1]), "+f"(d[2]), "+f"(d[3])
                 : "r"(a[0]), "r"(a[1]), "r"(a[2]), "r"(a[3]), "r"(b0), "r"(b1));
}

// ---------------- smem layout ----------------
#define AHI_OFF 0u       // 128 x 128B
#define ALO_OFF 16384u   // 128 x 128B
#define BHI_OFF 32768u   // 40 x 128B
#define BLO_OFF 37888u   // 40 x 128B
#define SMEM_BYTES 43008u

// ---------------- prep kernels ----------------
__global__ void prep_w(const float* __restrict__ W1, const float* __restrict__ W2) {
    int idx = blockIdx.x * 256 + threadIdx.x;
    if (idx >= KOFF * NPADB * CPAD) return;
    int j = idx & (CPAD - 1);
    int n = (idx / CPAD) % NPADB;
    int k = idx / (CPAD * NPADB);
    float w1 = (n < NOUT) ? W1[(k * 64 + j) * NOUT + n] : 0.0f;
    float w2 = (n < NOUT && j < NOUT) ? W2[(k * NOUT + j) * NOUT + n] : 0.0f;
    __nv_bfloat16 h1 = __float2bfloat16(w1);
    g_w1hi[idx] = h1;
    g_w1lo[idx] = __float2bfloat16(w1 - __bfloat162float(h1));
    __nv_bfloat16 h2 = __float2bfloat16(w2);
    g_w2hi[idx] = h2;
    g_w2lo[idx] = __float2bfloat16(w2 - __bfloat162float(h2));
}

__global__ void prep_f(const float* __restrict__ feat) {
    size_t idx = (size_t)blockIdx.x * 256 + threadIdx.x;
    if (idx >= (size_t)(NPTS + 1) * CPAD) return;
    size_t i = idx >> 6;
    float x = (i < NPTS) ? feat[idx] : 0.0f;
    __nv_bfloat16 h = __float2bfloat16(x);
    g_fhi[idx] = h;
    g_flo[idx] = __float2bfloat16(x - __bfloat162float(h));
    if (i == NPTS) {  // zero padding row of h
        g_hhi[idx] = __float2bfloat16(0.0f);
        g_hlo[idx] = __float2bfloat16(0.0f);
    }
}

// ---------------- main conv kernel: 4 warps x 32 rows, fused 3-pass split ----------------
template <int NKS, bool LAYER2>
__global__ void __launch_bounds__(128, 3) conv_mma(const int* __restrict__ nbr,
                                                   float* __restrict__ out) {
    __shared__ __align__(1024) char smb[SMEM_BYTES];
    const uint32_t smu = smem_u32(smb);
    const int t = threadIdx.x;
    const int lane = t & 31;
    const int wid = t >> 5;               // 0..3, warp owns rows [wid*32, wid*32+32)
    const int i0 = blockIdx.x * TILE_M;

    const __nv_bfloat16* __restrict__ shi = LAYER2 ? g_hhi : g_fhi;
    const __nv_bfloat16* __restrict__ slo = LAYER2 ? g_hlo : g_flo;
    const __nv_bfloat16* __restrict__ whi = LAYER2 ? g_w2hi : g_w1hi;
    const __nv_bfloat16* __restrict__ wlo = LAYER2 ? g_w2lo : g_w1lo;

    float acc[2][5][4];
#pragma unroll
    for (int mt = 0; mt < 2; ++mt)
#pragma unroll
        for (int nt = 0; nt < 5; ++nt)
#pragma unroll
            for (int q = 0; q < 4; ++q) acc[mt][nt][q] = 0.0f;

    // per-thread ldmatrix address components (constant across k)
    const int a_r = (lane & 7) + ((lane >> 3) & 1) * 8;
    const int a_half = (lane >> 4) << 4;     // 0 or 16 bytes
    const int b_r = lane & 7;
    const int b_sub = (lane >> 3) & 3;

    for (int k = 0; k < KOFF; ++k) {
        __syncthreads();  // protect smem from previous iteration's readers
        // ---- gather A (hi+lo): 128 rows x 8 chunks of 16B, swizzled ----
#pragma unroll
        for (int i = 0; i < 8; ++i) {
            int q = t + 128 * i;       // 0..1023
            int row = q >> 3, c = q & 7;
            int nb = __ldg(nbr + (size_t)k * NPTS + i0 + row);
            size_t src = (size_t)nb * CPAD + c * 8;
            uint32_t off = SWZ(row * 128 + c * 16);
            *(uint4*)(smb + AHI_OFF + off) = *(const uint4*)(shi + src);
            *(uint4*)(smb + ALO_OFF + off) = *(const uint4*)(slo + src);
        }
        // ---- B tile (hi+lo): 40 rows x 8 chunks ----
        {
            const __nv_bfloat16* wkh = whi + k * (NPADB * CPAD);
            const __nv_bfloat16* wkl = wlo + k * (NPADB * CPAD);
#pragma unroll
            for (int i = 0; i < 3; ++i) {
                int q = t + 128 * i;
                if (q < NPADB * 8) {
                    int row = q >> 3, c = q & 7;
                    uint32_t off = SWZ(row * 128 + c * 16);
                    *(uint4*)(smb + BHI_OFF + off) = *(const uint4*)(wkh + row * CPAD + c * 8);
                    *(uint4*)(smb + BLO_OFF + off) = *(const uint4*)(wkl + row * CPAD + c * 8);
                }
            }
        }
        __syncthreads();

        // ---- load ALL A fragments (hi+lo, both m-subtiles) once ----
        uint32_t ahi[2][NKS][4], alo[2][NKS][4];
#pragma unroll
        for (int mt = 0; mt < 2; ++mt) {
            const int arow = wid * 32 + mt * 16 + a_r;
#pragma unroll
            for (int ks = 0; ks < NKS; ++ks) {
                ldsm_x4(ahi[mt][ks], smu + AHI_OFF + SWZ(arow * 128 + ks * 32 + a_half));
                ldsm_x4(alo[mt][ks], smu + ALO_OFF + SWZ(arow * 128 + ks * 32 + a_half));
            }
        }

        // ---- single B sweep: each B frag (hi & lo) loaded once, all mmas issued ----
#pragma unroll
        for (int nt = 0; nt < 5; ++nt) {
            const int brow = nt * 8 + b_r;
#pragma unroll
            for (int ks2 = 0; ks2 < NKS / 2; ++ks2) {
                uint32_t bh[4], bl[4];
                ldsm_x4(bh, smu + BHI_OFF + SWZ(brow * 128 + ks2 * 64 + b_sub * 16));
                ldsm_x4(bl, smu + BLO_OFF + SWZ(brow * 128 + ks2 * 64 + b_sub * 16));
                // interleave m-subtiles to break acc dependency chains
                mma_bf16(acc[0][nt], ahi[0][2 * ks2],     bh[0], bh[1]);
                mma_bf16(acc[1][nt], ahi[1][2 * ks2],     bh[0], bh[1]);
                mma_bf16(acc[0][nt], ahi[0][2 * ks2 + 1], bh[2], bh[3]);
                mma_bf16(acc[1][nt], ahi[1][2 * ks2 + 1], bh[2], bh[3]);
                mma_bf16(acc[0][nt], alo[0][2 * ks2],     bh[0], bh[1]);
                mma_bf16(acc[1][nt], alo[1][2 * ks2],     bh[0], bh[1]);
                mma_bf16(acc[0][nt], alo[0][2 * ks2 + 1], bh[2], bh[3]);
                mma_bf16(acc[1][nt], alo[1][2 * ks2 + 1], bh[2], bh[3]);
                mma_bf16(acc[0][nt], ahi[0][2 * ks2],     bl[0], bl[1]);
                mma_bf16(acc[1][nt], ahi[1][2 * ks2],     bl[0], bl[1]);
                mma_bf16(acc[0][nt], ahi[0][2 * ks2 + 1], bl[2], bl[3]);
                mma_bf16(acc[1][nt], ahi[1][2 * ks2 + 1], bl[2], bl[3]);
            }
            if (NKS & 1) {
                uint32_t bh[2], bl[2];
                ldsm_x2(bh, smu + BHI_OFF + SWZ(brow * 128 + (NKS - 1) * 32 + (b_sub & 1) * 16));
                ldsm_x2(bl, smu + BLO_OFF + SWZ(brow * 128 + (NKS - 1) * 32 + (b_sub & 1) * 16));
                mma_bf16(acc[0][nt], ahi[0][NKS - 1], bh[0], bh[1]);
                mma_bf16(acc[1][nt], ahi[1][NKS - 1], bh[0], bh[1]);
                mma_bf16(acc[0][nt], alo[0][NKS - 1], bh[0], bh[1]);
                mma_bf16(acc[1][nt], alo[1][NKS - 1], bh[0], bh[1]);
                mma_bf16(acc[0][nt], ahi[0][NKS - 1], bl[0], bl[1]);
                mma_bf16(acc[1][nt], ahi[1][NKS - 1], bl[0], bl[1]);
            }
        }
    }

    // ---- epilogue ----
#pragma unroll
    for (int mt = 0; mt < 2; ++mt) {
        const int r1 = i0 + wid * 32 + mt * 16 + (lane >> 2);
#pragma unroll
        for (int half = 0; half < 2; ++half) {
            const int row = r1 + half * 8;
#pragma unroll
            for (int nt = 0; nt < 5; ++nt) {
                const int c = nt * 8 + (lane & 3) * 2;
                float v0 = acc[mt][nt][half * 2 + 0];
                float v1 = acc[mt][nt][half * 2 + 1];
                if (LAYER2) {
                    if (c < NOUT) {
                        float* o = out + (size_t)row * NOUT + c;
                        o[0] = v0;
                        if (c + 1 < NOUT) o[1] = v1;
                    }
                } else {
                    v0 = 0.5f * v0 * (1.0f + erff(v0 * 0.7071067811865475f));
                    v1 = 0.5f * v1 * (1.0f + erff(v1 * 0.7071067811865475f));
                    __nv_bfloat16 h0 = __float2bfloat16(v0), h1 = __float2bfloat16(v1);
                    __nv_bfloat162 hp; hp.x = h0; hp.y = h1;
                    *(__nv_bfloat162*)(g_hhi + (size_t)row * CPAD + c) = hp;
                    __nv_bfloat162 lp;
                    lp.x = __float2bfloat16(v0 - __bfloat162float(h0));
                    lp.y = __float2bfloat16(v1 - __bfloat162float(h1));
                    *(__nv_bfloat162*)(g_hlo + (size_t)row * CPAD + c) = lp;
                }
            }
        }
    }
}

// ---------------- launch ----------------
extern "C" void kernel_launch(void* const* d_in, const int* in_sizes, int n_in,
                              void* d_out, int out_size) {
    const float* feat = (const float*)d_in[0];  // [N, 64] f32
    const int* nbr    = (const int*)d_in[1];    // [27, N] i32
    const float* W1   = (const float*)d_in[2];  // [27, 64, 38] f32
    const float* W2   = (const float*)d_in[3];  // [27, 38, 38] f32
    float* out        = (float*)d_out;          // [N, 38] f32

    prep_w<<<(KOFF * NPADB * CPAD + 255) / 256, 256>>>(W1, W2);
    {
        size_t tot = (size_t)(NPTS + 1) * CPAD;
        prep_f<<<(unsigned)((tot + 255) / 256), 256>>>(feat);
    }
    conv_mma<4, false><<<NTILES, 128>>>(nbr, nullptr);  // layer1: K=64, GELU -> g_h (hi/lo)
    conv_mma<3, true ><<<NTILES, 128>>>(nbr, out);      // layer2: K=48 (38 padded)
}